// round 17
// baseline (speedup 1.0000x reference)
#include <cuda_runtime.h>
#include <cuda_bf16.h>
#include <cub/block/block_radix_sort.cuh>

// loss = (1/B) * sum_rows sum_{rank i<j} |t_i - t_j| * (dv_j - dv_i),  dv_k = log2(k+3)
// (sigmoid eliminated: sigma(x)+sigma(-x)=1; dv monotone increasing in rank.)
// K1: CUB radix 512x4 by pred desc, top-16 bits, payload target -> g_st. Zeroes out[0].
// K2: 36 UNIFORM blocks/row (28 rect tiles ai<ji + 8 diag tiles), every block = exactly
//     128 packed f32x2 iterations/thread -> zero imbalance. __launch_bounds__(256,8)
//     forces <=32 regs -> 8 blocks/SM -> grid 1152 fits in ONE wave (148*8=1184).

constexpr int BB = 32;
constexpr int NN = 2048;

typedef unsigned long long ull;

__device__ float g_st[BB * NN];

// 36 blocks per row: 28 rects (ai < ji) then 8 diags (ai == ji)
__constant__ unsigned char c_ai[36] = {
    0,0,0,0,0,0,0, 1,1,1,1,1,1, 2,2,2,2,2, 3,3,3,3, 4,4,4, 5,5, 6,
    0,1,2,3,4,5,6,7 };
__constant__ unsigned char c_ji[36] = {
    1,2,3,4,5,6,7, 2,3,4,5,6,7, 3,4,5,6,7, 4,5,6,7, 5,6,7, 6,7, 7,
    0,1,2,3,4,5,6,7 };

// ---------- packed f32x2 helpers ----------
__device__ __forceinline__ ull pk2(float lo, float hi) {
    ull r; asm("mov.b64 %0, {%1, %2};" : "=l"(r) : "f"(lo), "f"(hi)); return r;
}
__device__ __forceinline__ float sum2(ull v) {
    float lo, hi; asm("mov.b64 {%0, %1}, %2;" : "=f"(lo), "=f"(hi) : "l"(v));
    return lo + hi;
}
__device__ __forceinline__ ull add2(ull a, ull b) {
    ull r; asm("add.rn.f32x2 %0, %1, %2;" : "=l"(r) : "l"(a), "l"(b)); return r;
}
__device__ __forceinline__ ull fma2(ull a, ull b, ull c) {
    ull r; asm("fma.rn.f32x2 %0, %1, %2, %3;" : "=l"(r) : "l"(a), "l"(b), "l"(c)); return r;
}
__device__ __forceinline__ ull abs2(ull a) { return a & 0x7fffffff7fffffffULL; }

__device__ __forceinline__ unsigned mono32(unsigned u) {
    return (u & 0x80000000u) ? ~u : (u | 0x80000000u);
}

// ---------- K1: radix sort by pred desc (16 high bits), payload target ----------
using BRS = cub::BlockRadixSort<unsigned, 512, 4, unsigned>;

__global__ void __launch_bounds__(512) sort_kernel(const float* __restrict__ preds,
                                                   const float* __restrict__ targets,
                                                   float* __restrict__ out) {
    __shared__ typename BRS::TempStorage cubts;

    const int row = blockIdx.x;
    const int t   = threadIdx.x;
    if (row == 0 && t == 0) out[0] = 0.0f;   // stream-ordered before pair atomics

    const float4 pv = ((const float4*)(preds + row * NN))[t];
    const float4 tv = ((const float4*)(targets + row * NN))[t];

    unsigned keys[4] = { mono32(__float_as_uint(pv.x)), mono32(__float_as_uint(pv.y)),
                         mono32(__float_as_uint(pv.z)), mono32(__float_as_uint(pv.w)) };
    unsigned vals[4] = { __float_as_uint(tv.x), __float_as_uint(tv.y),
                         __float_as_uint(tv.z), __float_as_uint(tv.w) };

    BRS(cubts).SortDescending(keys, vals, 16, 32);   // 4 passes; near-tie swaps harmless

    ((float4*)(g_st + row * NN))[t] =
        make_float4(__uint_as_float(vals[0]), __uint_as_float(vals[1]),
                    __uint_as_float(vals[2]), __uint_as_float(vals[3]));
}

// ---------- K2: uniform-tile pair sum ----------
__global__ void __launch_bounds__(256, 8) pair_kernel(float* __restrict__ out) {
    __shared__ alignas(16) float ss[256];   // j-tile targets
    __shared__ alignas(16) float dd[256];   // j-tile dv
    __shared__ float wsum[8];

    const int row = blockIdx.y;
    const int b   = blockIdx.x;
    const int tid = threadIdx.x;

    const int ai = c_ai[b];
    const int ji = c_ji[b];

    const float* st = g_st + row * NN;
    const int jbase = ji * 256;

    ss[tid] = st[jbase + tid];
    dd[tid] = __log2f((float)(jbase + tid + 3));
    __syncthreads();

    float res;

    if (ai != ji) {
        // rect tile: a in [256*ai, +256), j in [jbase, +256); dv_j > da always
        const int a = ai * 256 + tid;
        const float ta = st[a];
        const float da = __log2f((float)(a + 3));
        const ull n = pk2(-ta, -ta);

        const ulonglong2* __restrict__ ps = (const ulonglong2*)ss;
        const ulonglong2* __restrict__ pd = (const ulonglong2*)dd;
        ull h0 = 0, h1 = 0, g0 = 0, g1 = 0;
#pragma unroll 8
        for (int q = 0; q < 64; q++) {
            ulonglong2 s2 = ps[q];
            ulonglong2 d2 = pd[q];
            ull u;
            u = abs2(add2(s2.x, n)); h1 = fma2(u, d2.x, h1); h0 = add2(h0, u);
            u = abs2(add2(s2.y, n)); g1 = fma2(u, d2.y, g1); g0 = add2(g0, u);
        }
        ull s1 = add2(h1, g1), s0 = add2(h0, g0);
        res = sum2(s1) - da * sum2(s0);
    } else {
        // diag tile: ordered pairs via sign-split on dv, scaled 0.5 (also 128 iters/thread)
        const float ta = ss[tid];
        const float da = dd[tid];
        const ull n = pk2(-ta, -ta);
        const ull* __restrict__ ps = (const ull*)ss;
        const ull* __restrict__ pd = (const ull*)dd;
        const int A = tid & ~1;

        ull l0 = 0, l1 = 0, h0 = 0, h1 = 0;
#pragma unroll 8
        for (int j = 0; j < (A >> 1); j++) {
            ull u = abs2(add2(ps[j], n));
            l1 = fma2(u, pd[j], l1);
            l0 = add2(l0, u);
        }
#pragma unroll 8
        for (int j = (A >> 1); j < 128; j++) {
            ull u = abs2(add2(ps[j], n));
            h1 = fma2(u, pd[j], h1);
            h0 = add2(h0, u);
        }
        res = (sum2(h1) - sum2(l1)) + da * (sum2(l0) - sum2(h0));
        if (tid & 1) {
            float u = fabsf(ss[A] - ta);
            res += 2.0f * u * (da - dd[A]);
        }
        res *= 0.5f;
    }

    // block reduction + single atomic per block (1152 total: ~fine)
#pragma unroll
    for (int off = 16; off > 0; off >>= 1)
        res += __shfl_down_sync(0xffffffffu, res, off);
    if ((tid & 31) == 0) wsum[tid >> 5] = res;
    __syncthreads();
    if (tid == 0) {
        float bs = 0.f;
#pragma unroll
        for (int w = 0; w < 8; w++) bs += wsum[w];
        atomicAdd(out, bs * (1.0f / (float)BB));
    }
}

extern "C" void kernel_launch(void* const* d_in, const int* in_sizes, int n_in,
                              void* d_out, int out_size) {
    const float* preds   = (const float*)d_in[0];
    const float* targets = (const float*)d_in[1];
    float* out = (float*)d_out;

    sort_kernel<<<BB, 512>>>(preds, targets, out);

    dim3 g2(36, BB);
    pair_kernel<<<g2, 256>>>(out);
}